// round 5
// baseline (speedup 1.0000x reference)
#include <cuda_runtime.h>
#include <cuda_bf16.h>
#include <cstdint>

#define NB 64
#define NN 256
#define INF_F 1e30f

// Transposed cost matrices: g_cmat[b][i][j] = costs[b][j][i]
// (rows = objects, cols = preds). 16 MB static scratch (no allocs allowed).
__device__ float g_cmat[NB * NN * NN];
__device__ int   g_len[NB];
__device__ int   g_costs_bf16;

// ---------------------------------------------------------------------------
// Kernel A: detect costs dtype (float32 vs bfloat16) on device.
// costs ~ N(0,1). Interpreted as bf16: if truly bf16, all finite, mean sq ~ 1.
// If actually f32, the low-half words decode to wild exponents -> detector
// trips. One block, 256 threads, reads first 4096 bf16 elements (within the
// buffer under both interpretations).
// ---------------------------------------------------------------------------
__global__ void detect_kernel(const void* __restrict__ costs) {
    const __nv_bfloat16* hb = (const __nv_bfloat16*)costs;
    const int t = threadIdx.x;
    float acc = 0.0f;
    int bad = 0;
    #pragma unroll
    for (int k = 0; k < 16; k++) {
        const float x = __bfloat162float(hb[t * 16 + k]);
        if (!isfinite(x) || fabsf(x) > 1e4f) bad++;
        else acc += x * x;
    }
    __shared__ float s_acc[8];
    __shared__ int   s_bad[8];
    #pragma unroll
    for (int o = 16; o; o >>= 1) {
        acc += __shfl_down_sync(0xFFFFFFFFu, acc, o);
        bad += __shfl_down_sync(0xFFFFFFFFu, bad, o);
    }
    if ((t & 31) == 0) { s_acc[t >> 5] = acc; s_bad[t >> 5] = bad; }
    __syncthreads();
    if (t == 0) {
        float ta = 0.0f; int tb = 0;
        #pragma unroll
        for (int k = 0; k < 8; k++) { ta += s_acc[k]; tb += s_bad[k]; }
        const float ms = ta / 4096.0f;
        g_costs_bf16 = (tb == 0 && ms > 0.1f && ms < 10.0f) ? 1 : 0;
    }
}

// ---------------------------------------------------------------------------
// Kernel 0: per-batch valid-object count. Robust to mask representation.
// lengths >= 128 guarantees element 0 is true, so the first 32-bit word
// disambiguates: 0x00000001 -> int32 bools; 0x3f800000 -> float32 bools;
// anything else (e.g. 0x01010101) -> 1-byte bools.
// ---------------------------------------------------------------------------
__global__ void length_kernel(const void* __restrict__ mask) {
    const unsigned w0 = *(const unsigned*)mask;
    const bool wide = (w0 == 1u) || (w0 == 0x3f800000u);
    const int b = blockIdx.x;
    const int t = threadIdx.x;  // 256 threads
    int nz;
    if (wide) {
        const unsigned* m = (const unsigned*)mask;
        nz = (m[b * NN + t] != 0u) ? 1 : 0;
    } else {
        const unsigned char* m = (const unsigned char*)mask;
        nz = (m[b * NN + t] != 0) ? 1 : 0;
    }
    __shared__ int s[8];
    const unsigned bal = __ballot_sync(0xFFFFFFFFu, nz);
    if ((t & 31) == 0) s[t >> 5] = __popc(bal);
    __syncthreads();
    if (t == 0) {
        int tot = 0;
        #pragma unroll
        for (int k = 0; k < 8; k++) tot += s[k];
        g_len[b] = tot;
    }
}

// ---------------------------------------------------------------------------
// Kernel 1: tiled transpose of each [256,256] batch, converting bf16->f32 if
// the detector flagged bf16 (exact upcast, identical to astype(float32)).
// ---------------------------------------------------------------------------
__global__ void transpose_kernel(const void* __restrict__ in) {
    __shared__ float t[32][33];
    const bool isbf = (g_costs_bf16 != 0);
    const int b  = blockIdx.z;
    const int j0 = blockIdx.x * 32;   // source row block (pred index)
    const int i0 = blockIdx.y * 32;   // source col block (object index)
    float* dst = g_cmat + (size_t)b * NN * NN;
    const int tx = threadIdx.x, ty = threadIdx.y;
    if (isbf) {
        const __nv_bfloat16* src = (const __nv_bfloat16*)in + (size_t)b * NN * NN;
        #pragma unroll
        for (int r = ty; r < 32; r += 8)
            t[r][tx] = __bfloat162float(src[(j0 + r) * NN + i0 + tx]);
    } else {
        const float* src = (const float*)in + (size_t)b * NN * NN;
        #pragma unroll
        for (int r = ty; r < 32; r += 8)
            t[r][tx] = src[(j0 + r) * NN + i0 + tx];
    }
    __syncthreads();
    #pragma unroll
    for (int r = ty; r < 32; r += 8)
        dst[(i0 + r) * NN + j0 + tx] = t[tx][r];
}

// ---------------------------------------------------------------------------
// Kernel 2: one warp per batch. FULL 256-row Jonker-Volgenant, exactly
// replicating the reference trajectory (invalid rows cost 0.0f, same FP op
// order, first-index argmin tie-break), then the reference's leftover rule.
// OUTPUT IS WRITTEN AS FLOAT32 VALUES (harness __output__ dtype).
// ---------------------------------------------------------------------------
__global__ void __launch_bounds__(32, 1) lap_kernel(float* __restrict__ out) {
    const int b    = blockIdx.x;
    const int lane = threadIdx.x;
    const float* __restrict__ C = g_cmat + (size_t)b * NN * NN;

    __shared__ float s_u[NN];
    __shared__ float s_sp[NN];
    __shared__ int   s_path[NN];
    __shared__ int   s_col4row[NN];
    __shared__ int   s_row4col[NN];
    __shared__ unsigned char s_SR[NN];

    const int nv = g_len[b];

    float v[8], sp[8];
    unsigned SC = 0;  // bit k: column k*32+lane in SC set
    #pragma unroll
    for (int k = 0; k < 8; k++) {
        const int idx = k * 32 + lane;
        v[k] = 0.0f;
        sp[k] = INF_F;
        s_u[idx] = 0.0f;
        s_sp[idx] = INF_F;
        s_path[idx] = -1;
        s_col4row[idx] = -1;
        s_row4col[idx] = -1;
        s_SR[idx] = 0;
        out[b * NN + idx] = (float)idx;  // defensive pre-fill (never poison)
    }
    __syncwarp();

    for (int cur = 0; cur < NN; cur++) {
        if (lane == 0) s_SR[cur] = 1;
        __syncwarp();
        int   i    = cur;
        float mv   = 0.0f;
        int   sink = -1;

        // ---------------- Dijkstra (shortest augmenting path) --------------
        for (;;) {
            const float ucur = s_u[i];
            const bool  zrow = (i >= nv);            // invalid row: cost 0.0f
            const float* __restrict__ row = C + i * NN;

            #pragma unroll
            for (int k = 0; k < 8; k++) {
                if (!((SC >> k) & 1u)) {
                    const float c = zrow ? 0.0f : row[k * 32 + lane];
                    const float r = ((mv + c) - ucur) - v[k];
                    if (r < sp[k]) {
                        sp[k] = r;
                        const int col = k * 32 + lane;
                        s_sp[col]   = r;
                        s_path[col] = i;
                    }
                }
            }

            // argmin with first-index tie-break (lexicographic (val, idx))
            float bv = INF_F;
            int   bi = NN;
            #pragma unroll
            for (int k = 0; k < 8; k++) {
                const float m = ((SC >> k) & 1u) ? INF_F : sp[k];
                const int idx = k * 32 + lane;
                if (m < bv || (m == bv && idx < bi)) { bv = m; bi = idx; }
            }
            #pragma unroll
            for (int o = 16; o; o >>= 1) {
                const float ov = __shfl_down_sync(0xFFFFFFFFu, bv, o);
                const int   oi = __shfl_down_sync(0xFFFFFFFFu, bi, o);
                if (ov < bv || (ov == bv && oi < bi)) { bv = ov; bi = oi; }
            }
            bv = __shfl_sync(0xFFFFFFFFu, bv, 0);
            bi = __shfl_sync(0xFFFFFFFFu, bi, 0);
            mv = bv;
            const int jmin = bi;

            if ((jmin & 31) == lane) SC |= 1u << (jmin >> 5);

            const int nxt = s_row4col[jmin];
            if (nxt < 0) { sink = jmin; break; }
            i = nxt;
            if (lane == 0) s_SR[nxt] = 1;
            __syncwarp();
        }
        __syncwarp();

        // ---------------- dual potential updates ----------------
        #pragma unroll
        for (int k = 0; k < 8; k++) {
            const int rrow = k * 32 + lane;
            if (s_SR[rrow]) {
                int cc = s_col4row[rrow];
                cc = (cc < 0) ? 0 : ((cc > NN - 1) ? NN - 1 : cc);  // ref clip
                const float du = (rrow == cur) ? mv : (mv - s_sp[cc]);
                s_u[rrow] += du;
            }
            if ((SC >> k) & 1u) v[k] -= (mv - sp[k]);
        }
        __syncwarp();

        // ---------------- augment along alternating path ----------------
        if (lane == 0) {
            int j = sink;
            int guard = 0;
            for (;;) {
                const int pi = s_path[j];
                s_row4col[j] = pi;
                const int jn = s_col4row[pi];
                s_col4row[pi] = j;
                if (pi == cur || ++guard > NN) break;
                j = jn;
            }
        }
        __syncwarp();

        // ---------------- reset for next augmentation ----------------
        SC = 0;
        #pragma unroll
        for (int k = 0; k < 8; k++) {
            const int idx = k * 32 + lane;
            sp[k] = INF_F;
            s_sp[idx] = INF_F;
            s_SR[idx] = 0;
        }
        __syncwarp();
    }

    // ---------------- write output (as float32 values) ----------------
    #pragma unroll
    for (int k = 0; k < 8; k++) {
        const int r = k * 32 + lane;
        if (r < nv) {
            int c = s_col4row[r];
            c = (c < 0) ? 0 : ((c > NN - 1) ? NN - 1 : c);
            out[b * NN + r] = (float)c;
        }
    }
    __syncwarp();
    if (lane == 0) {
        int pos = nv;
        for (int j = 0; j < NN; j++) {
            if (s_row4col[j] >= nv && pos < NN) out[b * NN + pos++] = (float)j;
        }
    }
}

// ---------------------------------------------------------------------------
extern "C" void kernel_launch(void* const* d_in, const int* in_sizes, int n_in,
                              void* d_out, int out_size) {
    // Identify inputs by element count instead of trusting position.
    const void* costs = d_in[0];
    const void* mask  = (n_in > 1) ? d_in[1] : d_in[0];
    for (int i = 0; i < n_in; i++) {
        if (in_sizes[i] == NB * NN * NN) costs = d_in[i];
        else if (in_sizes[i] == NB * NN) mask = d_in[i];
    }
    float* out = (float*)d_out;

    detect_kernel<<<1, NN>>>(costs);
    length_kernel<<<NB, NN>>>(mask);
    transpose_kernel<<<dim3(NN / 32, NN / 32, NB), dim3(32, 8)>>>(costs);
    lap_kernel<<<NB, 32>>>(out);
}

// round 6
// speedup vs baseline: 5.2200x; 5.2200x over previous
#include <cuda_runtime.h>
#include <cuda_bf16.h>
#include <cstdint>

#define NB 64
#define NN 256
#define INF_F 1e30f
#define FULLM 0xFFFFFFFFu

// Transposed cost matrices: g_cmat[b][i][j] = costs[b][j][i]
// (rows = objects, cols = preds). 16 MB static scratch.
__device__ float g_cmat[NB * NN * NN];

// ---------------------------------------------------------------------------
// Kernel 1: tiled transpose with inline costs-dtype detection (f32 vs bf16).
// Every thread checks the same first 64 bf16-interpreted elements: real bf16
// N(0,1) data -> all finite, |x| small, mean square ~1. f32 data read as bf16
// -> low-half words decode to wild exponents with prob ~0.45 each; P(miss)
// over 32 low-halves < 1e-8. Deterministic and identical across all blocks.
// ---------------------------------------------------------------------------
__global__ void transpose_kernel(const void* __restrict__ in) {
    const __nv_bfloat16* hb = (const __nv_bfloat16*)in;
    bool isbf = true;
    float acc = 0.0f;
    #pragma unroll
    for (int k = 0; k < 64; k++) {
        const float x = __bfloat162float(hb[k]);
        if (!isfinite(x) || fabsf(x) > 1e4f) isbf = false;
        else acc += x * x;
    }
    const float ms = acc * (1.0f / 64.0f);
    if (ms < 0.05f || ms > 20.0f) isbf = false;

    __shared__ float t[32][33];
    const int b  = blockIdx.z;
    const int j0 = blockIdx.x * 32;   // source row block (pred index)
    const int i0 = blockIdx.y * 32;   // source col block (object index)
    float* dst = g_cmat + (size_t)b * NN * NN;
    const int tx = threadIdx.x, ty = threadIdx.y;
    if (isbf) {
        const __nv_bfloat16* src = (const __nv_bfloat16*)in + (size_t)b * NN * NN;
        #pragma unroll
        for (int r = ty; r < 32; r += 8)
            t[r][tx] = __bfloat162float(src[(j0 + r) * NN + i0 + tx]);
    } else {
        const float* src = (const float*)in + (size_t)b * NN * NN;
        #pragma unroll
        for (int r = ty; r < 32; r += 8)
            t[r][tx] = src[(j0 + r) * NN + i0 + tx];
    }
    __syncthreads();
    #pragma unroll
    for (int r = ty; r < 32; r += 8)
        dst[(i0 + r) * NN + j0 + tx] = t[tx][r];
}

// ---------------------------------------------------------------------------
// Kernel 2: one warp per batch. Valid-rows-only Jonker-Volgenant
// (reference-identical FP op order and first-index argmin tie-break); the
// full-square reference's valid-row assignment equals this rectangular
// optimum (a.s. unique), and invalid rows are overwritten by the leftover
// rule either way. Inner loop: registers + read-only shared + global only.
// ---------------------------------------------------------------------------
__global__ void __launch_bounds__(32, 1) lap_kernel(const void* __restrict__ mask,
                                                    float* __restrict__ out) {
    const int b    = blockIdx.x;
    const int lane = threadIdx.x;
    const float* __restrict__ C = g_cmat + (size_t)b * NN * NN;

    __shared__ float s_u[NN];
    __shared__ float s_sp[NN];
    __shared__ int   s_path[NN];
    __shared__ int   s_col4row[NN];
    __shared__ int   s_row4col[NN];

    // ---- nv from mask (byte / int32 / float32 bools; elem 0 always true) ----
    const unsigned w0 = *(const unsigned*)mask;
    const bool wide = (w0 == 1u) || (w0 == 0x3f800000u);
    int nz = 0;
    if (wide) {
        const unsigned* m = (const unsigned*)mask + b * NN;
        #pragma unroll
        for (int k = 0; k < 8; k++) nz += (m[k * 32 + lane] != 0u) ? 1 : 0;
    } else {
        const unsigned char* m = (const unsigned char*)mask + b * NN;
        #pragma unroll
        for (int k = 0; k < 8; k++) nz += (m[k * 32 + lane] != 0) ? 1 : 0;
    }
    const int nv = __reduce_add_sync(FULLM, nz);

    // ---- init (lane owns columns/rows {k*32+lane}) ----
    float v[8], sp[8];
    int   path[8];
    #pragma unroll
    for (int k = 0; k < 8; k++) {
        const int idx = k * 32 + lane;
        v[k] = 0.0f;
        path[k] = -1;
        s_u[idx] = 0.0f;
        s_col4row[idx] = -1;
        s_row4col[idx] = -1;
        out[b * NN + idx] = (float)idx;  // defensive pre-fill
    }
    __syncwarp();

    for (int cur = 0; cur < nv; cur++) {
        unsigned SC  = 0;
        unsigned SRm = ((cur & 31) == lane) ? (1u << (cur >> 5)) : 0u;
        #pragma unroll
        for (int k = 0; k < 8; k++) sp[k] = INF_F;

        int   i    = cur;
        float mv   = 0.0f;   // minVal
        int   sink;

        // ---------------- Dijkstra (registers-only inner loop) --------------
        for (;;) {
            const float ucur = s_u[i];                    // LDS broadcast
            const float* __restrict__ row = C + i * NN;

            // relax non-SC columns; reference FP order:
            // r = ((minVal + cost) - u[i]) - v[j], strict <
            #pragma unroll
            for (int k = 0; k < 8; k++) {
                if (!((SC >> k) & 1u)) {
                    const float r = ((mv + row[k * 32 + lane]) - ucur) - v[k];
                    if (r < sp[k]) { sp[k] = r; path[k] = i; }
                }
            }

            // masked argmin with first-index tie-break via 2x REDUX
            unsigned bestOrd = 0xFFFFFFFFu;
            int      bestIdx = 0x7FFFFFFF;
            #pragma unroll
            for (int k = 0; k < 8; k++) {
                const float m = ((SC >> k) & 1u) ? INF_F : sp[k];
                const unsigned bits = __float_as_uint(m);
                const unsigned ord = (bits & 0x80000000u) ? ~bits
                                                          : (bits | 0x80000000u);
                if (ord < bestOrd) { bestOrd = ord; bestIdx = k * 32 + lane; }
            }
            const unsigned mOrd = __reduce_min_sync(FULLM, bestOrd);
            const unsigned cand = (bestOrd == mOrd) ? (unsigned)bestIdx
                                                    : 0xFFFFFFFFu;
            const int jmin = (int)__reduce_min_sync(FULLM, cand);
            mv = __uint_as_float((mOrd & 0x80000000u) ? (mOrd ^ 0x80000000u)
                                                      : ~mOrd);

            if ((jmin & 31) == lane) SC |= 1u << (jmin >> 5);

            const int nxt = s_row4col[jmin];              // LDS broadcast
            if (nxt < 0) { sink = jmin; break; }
            i = nxt;
            if ((nxt & 31) == lane) SRm |= 1u << (nxt >> 5);
        }

        // write back sp/path once for the random-access phases
        #pragma unroll
        for (int k = 0; k < 8; k++) {
            const int idx = k * 32 + lane;
            s_sp[idx]   = sp[k];
            s_path[idx] = path[k];
        }
        __syncwarp();

        // ---------------- dual potential updates ----------------
        #pragma unroll
        for (int k = 0; k < 8; k++) {
            const int rrow = k * 32 + lane;
            if ((SRm >> k) & 1u) {
                int cc = s_col4row[rrow];
                cc = (cc < 0) ? 0 : ((cc > NN - 1) ? NN - 1 : cc);  // ref clip
                const float du = (rrow == cur) ? mv : (mv - s_sp[cc]);
                s_u[rrow] += du;
            }
            if ((SC >> k) & 1u) v[k] -= (mv - sp[k]);
        }
        __syncwarp();

        // ---------------- augment along alternating path ----------------
        if (lane == 0) {
            int j = sink;
            for (;;) {
                const int pi = s_path[j];
                s_row4col[j] = pi;
                const int jn = s_col4row[pi];
                s_col4row[pi] = j;
                if (pi == cur) break;
                j = jn;
            }
        }
        __syncwarp();
    }

    // ---------------- write output (float32 values) ----------------
    #pragma unroll
    for (int k = 0; k < 8; k++) {
        const int r = k * 32 + lane;
        if (r < nv) {
            int c = s_col4row[r];
            c = (c < 0) ? 0 : ((c > NN - 1) ? NN - 1 : c);
            out[b * NN + r] = (float)c;
        }
    }
    __syncwarp();
    if (lane == 0) {
        int pos = nv;
        for (int j = 0; j < NN; j++) {
            if (s_row4col[j] < 0 && pos < NN) out[b * NN + pos++] = (float)j;
        }
    }
}

// ---------------------------------------------------------------------------
extern "C" void kernel_launch(void* const* d_in, const int* in_sizes, int n_in,
                              void* d_out, int out_size) {
    // Identify inputs by element count instead of trusting position.
    const void* costs = d_in[0];
    const void* mask  = (n_in > 1) ? d_in[1] : d_in[0];
    for (int i = 0; i < n_in; i++) {
        if (in_sizes[i] == NB * NN * NN) costs = d_in[i];
        else if (in_sizes[i] == NB * NN) mask = d_in[i];
    }
    float* out = (float*)d_out;

    transpose_kernel<<<dim3(NN / 32, NN / 32, NB), dim3(32, 8)>>>(costs);
    lap_kernel<<<NB, 32>>>(mask, out);
}

// round 7
// speedup vs baseline: 15.9992x; 3.0650x over previous
#include <cuda_runtime.h>
#include <cuda_bf16.h>
#include <cstdint>

#define NB 64
#define NN 256
#define INF_F 1e30f
#define FULLM 0xFFFFFFFFu
#define RROWS 220                       // cost rows staged in shared memory
#define SMEM_BYTES (RROWS * NN * 4 + 5 * NN * 4)   // 230400 B <= 227 KB

// Transposed cost matrices: g_cmat[b][i][j] = costs[b][j][i]
// (rows = objects, cols = preds). 16 MB static scratch.
__device__ float g_cmat[NB * NN * NN];

// ---------------------------------------------------------------------------
// Kernel 1: tiled transpose with inline costs-dtype detection (f32 vs bf16).
// Every thread checks the same first 64 bf16-interpreted elements: real bf16
// N(0,1) -> all finite, mean square ~1. f32 read as bf16 -> low-half words
// decode to wild exponents w.p. ~0.45 each; P(miss) < 1e-8. Deterministic.
// ---------------------------------------------------------------------------
__global__ void transpose_kernel(const void* __restrict__ in) {
    const __nv_bfloat16* hb = (const __nv_bfloat16*)in;
    bool isbf = true;
    float acc = 0.0f;
    #pragma unroll
    for (int k = 0; k < 64; k++) {
        const float x = __bfloat162float(hb[k]);
        if (!isfinite(x) || fabsf(x) > 1e4f) isbf = false;
        else acc += x * x;
    }
    const float ms = acc * (1.0f / 64.0f);
    if (ms < 0.05f || ms > 20.0f) isbf = false;

    __shared__ float t[32][33];
    const int b  = blockIdx.z;
    const int j0 = blockIdx.x * 32;   // source row block (pred index)
    const int i0 = blockIdx.y * 32;   // source col block (object index)
    float* dst = g_cmat + (size_t)b * NN * NN;
    const int tx = threadIdx.x, ty = threadIdx.y;
    if (isbf) {
        const __nv_bfloat16* src = (const __nv_bfloat16*)in + (size_t)b * NN * NN;
        #pragma unroll
        for (int r = ty; r < 32; r += 8)
            t[r][tx] = __bfloat162float(src[(j0 + r) * NN + i0 + tx]);
    } else {
        const float* src = (const float*)in + (size_t)b * NN * NN;
        #pragma unroll
        for (int r = ty; r < 32; r += 8)
            t[r][tx] = src[(j0 + r) * NN + i0 + tx];
    }
    __syncthreads();
    #pragma unroll
    for (int r = ty; r < 32; r += 8)
        dst[(i0 + r) * NN + j0 + tx] = t[tx][r];
}

// ---------------------------------------------------------------------------
// Kernel 2: one warp per batch, valid-rows-only Jonker-Volgenant with the
// reference-identical FP op order and first-index argmin tie-break.
// Cost rows 0..RROWS-1 are staged in shared memory (29-cy LDS instead of
// L1/L2-latency LDG on the serial critical path); rows >= RROWS (<= 36 KB)
// stay in L1. Inner loop: registers + LDS only.
// ---------------------------------------------------------------------------
__global__ void __launch_bounds__(32, 1) lap_kernel(const void* __restrict__ mask,
                                                    float* __restrict__ out) {
    extern __shared__ unsigned char s_raw[];
    float* s_cost = (float*)s_raw;                       // [RROWS][NN]
    float* s_u    = (float*)(s_raw + RROWS * NN * 4);
    float* s_sp   = s_u + NN;
    int*   s_path = (int*)(s_sp + NN);
    int*   s_c4r  = s_path + NN;
    int*   s_r4c  = s_c4r + NN;

    const int b    = blockIdx.x;
    const int lane = threadIdx.x;
    const float* __restrict__ C = g_cmat + (size_t)b * NN * NN;

    // ---- nv from mask (byte / int32 / float32 bools; elem 0 always true) ---
    const unsigned w0 = *(const unsigned*)mask;
    const bool wide = (w0 == 1u) || (w0 == 0x3f800000u);
    int nz = 0;
    if (wide) {
        const unsigned* m = (const unsigned*)mask + b * NN;
        #pragma unroll
        for (int k = 0; k < 8; k++) nz += (m[k * 32 + lane] != 0u) ? 1 : 0;
    } else {
        const unsigned char* m = (const unsigned char*)mask + b * NN;
        #pragma unroll
        for (int k = 0; k < 8; k++) nz += (m[k * 32 + lane] != 0) ? 1 : 0;
    }
    const int nv = __reduce_add_sync(FULLM, nz);

    // ---- stage cost rows [0, min(nv,RROWS)) into shared memory ----
    {
        const int nrow = (nv < RROWS) ? nv : RROWS;
        const int nvec = nrow * (NN / 4);                // float4 count
        const float4* __restrict__ src = (const float4*)C;
        float4* dst = (float4*)s_cost;
        for (int t = lane; t < nvec; t += 32) dst[t] = src[t];
    }

    // ---- init (lane owns columns/rows {k*32+lane}) ----
    float v[8], sp[8];
    unsigned ord[8];                     // monotonic-encoded sp (cached)
    int path[8];
    #pragma unroll
    for (int k = 0; k < 8; k++) {
        const int idx = k * 32 + lane;
        v[k] = 0.0f;
        path[k] = -1;
        s_u[idx] = 0.0f;
        s_c4r[idx] = -1;
        s_r4c[idx] = -1;
        out[b * NN + idx] = (float)idx;  // defensive pre-fill
    }
    __syncwarp();

    for (int cur = 0; cur < nv; cur++) {
        unsigned SC  = 0;
        unsigned SRm = ((cur & 31) == lane) ? (1u << (cur >> 5)) : 0u;
        #pragma unroll
        for (int k = 0; k < 8; k++) { sp[k] = INF_F; ord[k] = 0xFFFFFFFEu; }

        int   i  = cur;
        float mv = 0.0f;                 // minVal
        int   sink;

        // ---------------- Dijkstra (LDS + registers inner loop) ------------
        for (;;) {
            const float ucur = s_u[i];
            float cv[8];
            if (i < RROWS) {
                const float* __restrict__ r = s_cost + i * NN;
                #pragma unroll
                for (int k = 0; k < 8; k++) cv[k] = r[k * 32 + lane];
            } else {
                const float* __restrict__ r = C + i * NN;
                #pragma unroll
                for (int k = 0; k < 8; k++) cv[k] = __ldg(r + k * 32 + lane);
            }

            // relax (reference FP order) + refresh encoded keys on improve
            #pragma unroll
            for (int k = 0; k < 8; k++) {
                if (!((SC >> k) & 1u)) {
                    const float rr = ((mv + cv[k]) - ucur) - v[k];
                    if (rr < sp[k]) {
                        sp[k] = rr;
                        path[k] = i;
                        const unsigned bits = __float_as_uint(rr);
                        ord[k] = (bits & 0x80000000u) ? ~bits
                                                      : (bits | 0x80000000u);
                    }
                }
            }

            // local argmin (first-k tie-break), SC masked by select
            unsigned bestOrd = 0xFFFFFFFFu;
            int      bestIdx = 0x7FFFFFFF;
            #pragma unroll
            for (int k = 0; k < 8; k++) {
                const unsigned o = ((SC >> k) & 1u) ? 0xFFFFFFFFu : ord[k];
                if (o < bestOrd) { bestOrd = o; bestIdx = k * 32 + lane; }
            }
            // cross-lane argmin with exact first-index tie-break (2x REDUX)
            const unsigned mOrd = __reduce_min_sync(FULLM, bestOrd);
            const unsigned cand = (bestOrd == mOrd) ? (unsigned)bestIdx
                                                    : 0x7FFFFFFFu;
            const int jmin = (int)__reduce_min_sync(FULLM, cand);
            mv = __uint_as_float((mOrd & 0x80000000u) ? (mOrd ^ 0x80000000u)
                                                      : ~mOrd);

            if ((jmin & 31) == lane) SC |= 1u << (jmin >> 5);

            const int nxt = s_r4c[jmin];                 // LDS broadcast
            if (nxt < 0) { sink = jmin; break; }
            i = nxt;
            if ((nxt & 31) == lane) SRm |= 1u << (nxt >> 5);
        }

        // write back sp/path once for the random-access phases
        #pragma unroll
        for (int k = 0; k < 8; k++) {
            const int idx = k * 32 + lane;
            s_sp[idx]   = sp[k];
            s_path[idx] = path[k];
        }
        __syncwarp();

        // ---------------- dual potential updates ----------------
        #pragma unroll
        for (int k = 0; k < 8; k++) {
            const int rrow = k * 32 + lane;
            if ((SRm >> k) & 1u) {
                int cc = s_c4r[rrow];
                cc = (cc < 0) ? 0 : ((cc > NN - 1) ? NN - 1 : cc);  // ref clip
                const float du = (rrow == cur) ? mv : (mv - s_sp[cc]);
                s_u[rrow] += du;
            }
            if ((SC >> k) & 1u) v[k] -= (mv - sp[k]);
        }
        __syncwarp();

        // ---------------- augment along alternating path ----------------
        if (lane == 0) {
            int j = sink;
            for (;;) {
                const int pi = s_path[j];
                s_r4c[j] = pi;
                const int jn = s_c4r[pi];
                s_c4r[pi] = j;
                if (pi == cur) break;
                j = jn;
            }
        }
        __syncwarp();
    }

    // ---------------- write output (float32 values) ----------------
    #pragma unroll
    for (int k = 0; k < 8; k++) {
        const int r = k * 32 + lane;
        if (r < nv) {
            int c = s_c4r[r];
            c = (c < 0) ? 0 : ((c > NN - 1) ? NN - 1 : c);
            out[b * NN + r] = (float)c;
        }
    }
    __syncwarp();
    if (lane == 0) {
        int pos = nv;
        for (int j = 0; j < NN; j++) {
            if (s_r4c[j] < 0 && pos < NN) out[b * NN + pos++] = (float)j;
        }
    }
}

// ---------------------------------------------------------------------------
extern "C" void kernel_launch(void* const* d_in, const int* in_sizes, int n_in,
                              void* d_out, int out_size) {
    // Identify inputs by element count instead of trusting position.
    const void* costs = d_in[0];
    const void* mask  = (n_in > 1) ? d_in[1] : d_in[0];
    for (int i = 0; i < n_in; i++) {
        if (in_sizes[i] == NB * NN * NN) costs = d_in[i];
        else if (in_sizes[i] == NB * NN) mask = d_in[i];
    }
    float* out = (float*)d_out;

    cudaFuncSetAttribute(lap_kernel,
                         cudaFuncAttributeMaxDynamicSharedMemorySize,
                         SMEM_BYTES);

    transpose_kernel<<<dim3(NN / 32, NN / 32, NB), dim3(32, 8)>>>(costs);
    lap_kernel<<<NB, 32, SMEM_BYTES>>>(mask, out);
}

// round 9
// speedup vs baseline: 26.2356x; 1.6398x over previous
#include <cuda_runtime.h>
#include <cuda_bf16.h>
#include <cstdint>

#define NB 64
#define NN 256
#define INF_F 1e30f
#define FULLM 0xFFFFFFFFu
#define RROWS 220                       // cost rows staged in shared memory
#define SMEM_BYTES (RROWS * NN * 4 + 5 * NN * 4)   // 230400 B <= 227 KB

// Transposed cost matrices: g_cmat[b][i][j] = costs[b][j][i]
// (rows = objects, cols = preds). 16 MB static scratch.
__device__ float g_cmat[NB * NN * NN];

// ---------------------------------------------------------------------------
// Kernel 1: tiled transpose with inline costs-dtype detection (f32 vs bf16).
// ---------------------------------------------------------------------------
__global__ void transpose_kernel(const void* __restrict__ in) {
    const __nv_bfloat16* hb = (const __nv_bfloat16*)in;
    bool isbf = true;
    float acc = 0.0f;
    #pragma unroll
    for (int k = 0; k < 64; k++) {
        const float x = __bfloat162float(hb[k]);
        if (!isfinite(x) || fabsf(x) > 1e4f) isbf = false;
        else acc += x * x;
    }
    const float ms = acc * (1.0f / 64.0f);
    if (ms < 0.05f || ms > 20.0f) isbf = false;

    __shared__ float t[32][33];
    const int b  = blockIdx.z;
    const int j0 = blockIdx.x * 32;   // source row block (pred index)
    const int i0 = blockIdx.y * 32;   // source col block (object index)
    float* dst = g_cmat + (size_t)b * NN * NN;
    const int tx = threadIdx.x, ty = threadIdx.y;
    if (isbf) {
        const __nv_bfloat16* src = (const __nv_bfloat16*)in + (size_t)b * NN * NN;
        #pragma unroll
        for (int r = ty; r < 32; r += 8)
            t[r][tx] = __bfloat162float(src[(j0 + r) * NN + i0 + tx]);
    } else {
        const float* src = (const float*)in + (size_t)b * NN * NN;
        #pragma unroll
        for (int r = ty; r < 32; r += 8)
            t[r][tx] = src[(j0 + r) * NN + i0 + tx];
    }
    __syncthreads();
    #pragma unroll
    for (int r = ty; r < 32; r += 8)
        dst[(i0 + r) * NN + j0 + tx] = t[tx][r];
}

// ---------------------------------------------------------------------------
// Kernel 2: one warp per batch, valid-rows-only Jonker-Volgenant,
// reference-identical FP op order and first-index argmin tie-break.
// Per-step chain: REDUX2 (carries jmin AND next row packed) -> LDS cost row
// -> relax -> FMNMX tree -> REDUX1 -> select -> REDUX2.
// ---------------------------------------------------------------------------
__global__ void __launch_bounds__(32, 1) lap_kernel(const void* __restrict__ mask,
                                                    float* __restrict__ out) {
    extern __shared__ unsigned char s_raw[];
    float* s_cost = (float*)s_raw;                       // [RROWS][NN]
    float* s_u    = (float*)(s_raw + RROWS * NN * 4);
    float* s_sp   = s_u + NN;
    int*   s_path = (int*)(s_sp + NN);
    int*   s_c4r  = s_path + NN;
    int*   s_r4c  = s_c4r + NN;

    const int b    = blockIdx.x;
    const int lane = threadIdx.x;
    const float* __restrict__ C = g_cmat + (size_t)b * NN * NN;

    // ---- nv from mask (byte / int32 / float32 bools; elem 0 always true) ---
    const unsigned w0 = *(const unsigned*)mask;
    const bool wide = (w0 == 1u) || (w0 == 0x3f800000u);
    int nz = 0;
    if (wide) {
        const unsigned* m = (const unsigned*)mask + b * NN;
        #pragma unroll
        for (int k = 0; k < 8; k++) nz += (m[k * 32 + lane] != 0u) ? 1 : 0;
    } else {
        const unsigned char* m = (const unsigned char*)mask + b * NN;
        #pragma unroll
        for (int k = 0; k < 8; k++) nz += (m[k * 32 + lane] != 0) ? 1 : 0;
    }
    const int nv = __reduce_add_sync(FULLM, nz);

    // ---- stage cost rows [0, min(nv,RROWS)) into shared memory ----
    {
        const int nrow = (nv < RROWS) ? nv : RROWS;
        const int nvec = nrow * (NN / 4);                // float4 count
        const float4* __restrict__ src = (const float4*)C;
        float4* dst = (float4*)s_cost;
        for (int t = lane; t < nvec; t += 32) dst[t] = src[t];
    }

    // ---- init (lane owns columns/rows {k*32+lane}) ----
    float v[8], sp[8], spm[8];
    int path[8], r4cr[8];
    #pragma unroll
    for (int k = 0; k < 8; k++) {
        const int idx = k * 32 + lane;
        v[k] = 0.0f;
        path[k] = -1;
        s_u[idx] = 0.0f;
        s_c4r[idx] = -1;
        s_r4c[idx] = -1;
        out[b * NN + idx] = (float)idx;  // defensive pre-fill
    }
    __syncwarp();

    for (int cur = 0; cur < nv; cur++) {
        unsigned SC  = 0;
        unsigned SRm = ((cur & 31) == lane) ? (1u << (cur >> 5)) : 0u;
        #pragma unroll
        for (int k = 0; k < 8; k++) {
            sp[k] = INF_F;
            spm[k] = INF_F;
            r4cr[k] = s_r4c[k * 32 + lane];   // snapshot (constant this run)
        }

        int   i  = cur;
        float mv = 0.0f;                 // minVal
        int   sink;

        // ---------------- Dijkstra ----------------
        for (;;) {
            const float ucur = s_u[i];
            float cv[8];
            if (i < RROWS) {
                const float* __restrict__ r = s_cost + i * NN;
                #pragma unroll
                for (int k = 0; k < 8; k++) cv[k] = r[k * 32 + lane];
            } else {
                const float* __restrict__ r = C + i * NN;
                #pragma unroll
                for (int k = 0; k < 8; k++) cv[k] = __ldg(r + k * 32 + lane);
            }

            // relax (reference FP order), SC-gated, updates sp/spm/path
            #pragma unroll
            for (int k = 0; k < 8; k++) {
                const float rr = ((mv + cv[k]) - ucur) - v[k];
                const bool p = (rr < sp[k]) && !((SC >> k) & 1u);
                if (p) { sp[k] = rr; spm[k] = rr; path[k] = i; }
            }

            // local min via balanced FMNMX tree (12 cy on chain)
            const float m01 = fminf(spm[0], spm[1]);
            const float m23 = fminf(spm[2], spm[3]);
            const float m45 = fminf(spm[4], spm[5]);
            const float m67 = fminf(spm[6], spm[7]);
            const float m03 = fminf(m01, m23);
            const float m47 = fminf(m45, m67);
            const float mloc = fminf(m03, m47);

            // encode winner value for cross-lane REDUX (monotonic uint order)
            const unsigned bm  = __float_as_uint(mloc);
            const unsigned ord = (bm & 0x80000000u) ? ~bm : (bm | 0x80000000u);
            const unsigned mOrd = __reduce_min_sync(FULLM, ord);

            // off-chain (parallel with REDUX1): lowest-k index + its row4col
            unsigned bits = 0;
            #pragma unroll
            for (int k = 0; k < 8; k++)
                if (spm[k] == mloc) bits |= 1u << k;
            const unsigned oneh = bits & (unsigned)(-(int)bits);
            int nxtl1 = 0;
            #pragma unroll
            for (int k = 0; k < 8; k++)
                nxtl1 += (int)((oneh >> k) & 1u) * (r4cr[k] + 1);
            const int kf = __ffs(bits) - 1;
            const unsigned bestIdx = (unsigned)(kf * 32 + lane);

            // packed candidate: [idx:8][row4col+1:9]; min over lanes = exact
            // lowest-index tie-break, and winner carries the next row for free
            const unsigned cand = (ord == mOrd)
                                ? ((bestIdx << 9) | (unsigned)nxtl1)
                                : 0x7FFFFFFFu;
            const unsigned cw = __reduce_min_sync(FULLM, cand);
            const int jmin = (int)(cw >> 9);
            const int nxt  = (int)(cw & 511u) - 1;

            // mv decode (off-chain w.r.t. next row fetch)
            const unsigned mb = (mOrd & 0x80000000u) ? (mOrd ^ 0x80000000u)
                                                     : ~mOrd;
            mv = __uint_as_float(mb);

            if ((jmin & 31) == lane) {
                const int kk = jmin >> 5;
                SC |= 1u << kk;
                spm[kk] = INF_F;           // sp[kk] stays frozen (true value)
            }
            if (nxt < 0) { sink = jmin; break; }
            i = nxt;
            if ((nxt & 31) == lane) SRm |= 1u << (nxt >> 5);
        }

        // write back sp/path for the random-access phases
        #pragma unroll
        for (int k = 0; k < 8; k++) {
            const int idx = k * 32 + lane;
            s_sp[idx]   = sp[k];
            s_path[idx] = path[k];
        }
        __syncwarp();

        // ---------------- dual potential updates ----------------
        #pragma unroll
        for (int k = 0; k < 8; k++) {
            const int rrow = k * 32 + lane;
            if ((SRm >> k) & 1u) {
                int cc = s_c4r[rrow];
                cc = (cc < 0) ? 0 : ((cc > NN - 1) ? NN - 1 : cc);  // ref clip
                const float du = (rrow == cur) ? mv : (mv - s_sp[cc]);
                s_u[rrow] += du;
            }
            if ((SC >> k) & 1u) v[k] -= (mv - sp[k]);
        }
        __syncwarp();

        // ---------------- augment along alternating path ----------------
        if (lane == 0) {
            int j = sink;
            for (;;) {
                const int pi = s_path[j];
                s_r4c[j] = pi;
                const int jn = s_c4r[pi];
                s_c4r[pi] = j;
                if (pi == cur) break;
                j = jn;
            }
        }
        __syncwarp();
    }

    // ---------------- write output (float32 values) ----------------
    #pragma unroll
    for (int k = 0; k < 8; k++) {
        const int r = k * 32 + lane;
        if (r < nv) {
            int c = s_c4r[r];
            c = (c < 0) ? 0 : ((c > NN - 1) ? NN - 1 : c);
            out[b * NN + r] = (float)c;
        }
    }
    __syncwarp();
    if (lane == 0) {
        int pos = nv;
        for (int j = 0; j < NN; j++) {
            if (s_r4c[j] < 0 && pos < NN) out[b * NN + pos++] = (float)j;
        }
    }
}

// ---------------------------------------------------------------------------
extern "C" void kernel_launch(void* const* d_in, const int* in_sizes, int n_in,
                              void* d_out, int out_size) {
    const void* costs = d_in[0];
    const void* mask  = (n_in > 1) ? d_in[1] : d_in[0];
    for (int i = 0; i < n_in; i++) {
        if (in_sizes[i] == NB * NN * NN) costs = d_in[i];
        else if (in_sizes[i] == NB * NN) mask = d_in[i];
    }
    float* out = (float*)d_out;

    cudaFuncSetAttribute(lap_kernel,
                         cudaFuncAttributeMaxDynamicSharedMemorySize,
                         SMEM_BYTES);

    transpose_kernel<<<dim3(NN / 32, NN / 32, NB), dim3(32, 8)>>>(costs);
    lap_kernel<<<NB, 32, SMEM_BYTES>>>(mask, out);
}